// round 16
// baseline (speedup 1.0000x reference)
#include <cuda_runtime.h>
#include <cuda_fp16.h>
#include <math.h>
#include <stdint.h>

#define N_NODES 20000
#define NE      160000
#define HIDDEN  512
#define QKVDIM  1536
#define NREL    128
#define NHEAD   8
#define DKEY    64
#define NLAYER  4
#define FFDIM   2048
#define MPAD    20096   // 157 * 128
#define SCALE   0.125f

// ---------------- device scratch ----------------
__device__ float  g_x  [(size_t)MPAD * HIDDEN];
__device__ __half g_xh [(size_t)MPAD * HIDDEN];
__device__ __half g_qkvh[(size_t)MPAD * QKVDIM];
__device__ __half g_wvh[(size_t)MPAD * HIDDEN];
__device__ __half g_oh [(size_t)MPAD * HIDDEN];
__device__ float  g_h  [(size_t)MPAD * HIDDEN];
__device__ __half g_hh [(size_t)MPAD * HIDDEN];
__device__ __half g_ffh[(size_t)MPAD * FFDIM];
__device__ __half g_f2h[(size_t)MPAD * HIDDEN];
__device__ __half g_relh[NREL * HIDDEN];

// CSR
__device__ int g_deg[N_NODES];
__device__ int g_cur[N_NODES];
__device__ int g_off[N_NODES + 1];
__device__ int g_eid[NE];

// fp16 weights, transposed to [N][K] per GEMM. per layer: QKV, O, W1, W2
#define L_QKV 0
#define L_O   (HIDDEN * QKVDIM)
#define L_W1  (L_O + HIDDEN * HIDDEN)
#define L_W2  (L_W1 + HIDDEN * FFDIM)
#define WT_LAYER (L_W2 + FFDIM * HIDDEN)
__device__ __half g_wrh[(size_t)NLAYER * WT_LAYER];
__device__ float  g_bqkv[NLAYER * QKVDIM];

// ---------------- helpers ----------------
__device__ __forceinline__ uint32_t smem_u32(const void* p) {
    return (uint32_t)__cvta_generic_to_shared(p);
}
__device__ __forceinline__ void cp_async16(uint32_t smem_dst, const void* gmem_src) {
    asm volatile("cp.async.cg.shared.global [%0], [%1], 16;\n" :: "r"(smem_dst), "l"(gmem_src));
}
__device__ __forceinline__ void cp_commit() {
    asm volatile("cp.async.commit_group;\n");
}
template <int N>
__device__ __forceinline__ void cp_wait() {
    asm volatile("cp.async.wait_group %0;\n" :: "n"(N));
}
__device__ __forceinline__ void mma16816(float& d0, float& d1, float& d2, float& d3,
                                         uint32_t a0, uint32_t a1, uint32_t a2, uint32_t a3,
                                         uint32_t b0, uint32_t b1) {
    asm volatile(
        "mma.sync.aligned.m16n8k16.row.col.f32.f16.f16.f32 "
        "{%0,%1,%2,%3}, {%4,%5,%6,%7}, {%8,%9}, {%0,%1,%2,%3};\n"
        : "+f"(d0), "+f"(d1), "+f"(d2), "+f"(d3)
        : "r"(a0), "r"(a1), "r"(a2), "r"(a3), "r"(b0), "r"(b1));
}
__device__ __forceinline__ void ldsm_x4(uint32_t& r0, uint32_t& r1, uint32_t& r2, uint32_t& r3,
                                        uint32_t addr) {
    asm volatile("ldmatrix.sync.aligned.m8n8.x4.shared.b16 {%0,%1,%2,%3}, [%4];"
                 : "=r"(r0), "=r"(r1), "=r"(r2), "=r"(r3) : "r"(addr));
}

// ---------------- persistent fp16 GEMM (fp32 accum) ----------------
// CTA 128x128, 4 warps (2x2), warp 64x64, K-chunk 64, 3-stage cp.async, ldmatrix.x4.
#define ASH 72
#define A_BYTES (128 * ASH * 2)      // 18432
#define STAGE_BYTES (2 * A_BYTES)    // 36864
#define NSTAGE 3
#define GEMM_SMEM (NSTAGE * STAGE_BYTES)   // 110,592 B

template<int RELU, int HOUT>
__global__ __launch_bounds__(128, 2)
void gemm_h(const __half* __restrict__ A, const __half* __restrict__ B,
            const float* __restrict__ bias, void* __restrict__ Cv,
            int K, int Nd) {
    extern __shared__ char smraw[];

    int tid = threadIdx.x;
    int warp = tid >> 5, lane = tid & 31;
    int wm = warp >> 1, wn = warp & 1;
    int g = lane >> 2, tg = lane & 3;
    int mi = lane >> 3, lr = lane & 7;
    const int KT = K >> 6;
    const int ntx = Nd >> 7;
    const int num_tiles = ntx * (MPAD >> 7);

    uint32_t aoff[4];
#pragma unroll
    for (int mt = 0; mt < 4; mt++)
        aoff[mt] = (uint32_t)((wm * 64 + mt * 16 + (mi & 1) * 8 + lr) * 144 + (mi >> 1) * 16);
    uint32_t boff[4];
#pragma unroll
    for (int p = 0; p < 4; p++)
        boff[p] = (uint32_t)((wn * 64 + p * 16 + (mi >> 1) * 8 + lr) * 144 + (mi & 1) * 16);

    for (int tile = blockIdx.x; tile < num_tiles; tile += gridDim.x) {
        int row0 = (tile / ntx) * 128;
        int col0 = (tile % ntx) * 128;

        float acc[4][8][4];
#pragma unroll
        for (int nt = 0; nt < 8; nt++) {
            int col = col0 + wn * 64 + nt * 8 + tg * 2;
            float b0 = bias[col], b1 = bias[col + 1];
#pragma unroll
            for (int mt = 0; mt < 4; mt++) {
                acc[mt][nt][0] = b0; acc[mt][nt][1] = b1;
                acc[mt][nt][2] = b0; acc[mt][nt][3] = b1;
            }
        }

        auto load_stage = [&](int stage, int kt) {
            uint32_t sA = smem_u32(smraw) + stage * STAGE_BYTES;
            uint32_t sB = sA + A_BYTES;
            int k0 = kt << 6;
#pragma unroll
            for (int i = 0; i < 16; i++) {
                int c = tid + i * 128;
                if (c < 1024) {
                    int row = c >> 3, c16 = c & 7;
                    cp_async16(sA + (uint32_t)(row * 144 + c16 * 16),
                               A + (size_t)(row0 + row) * K + k0 + c16 * 8);
                } else {
                    int cc = c - 1024;
                    int n = cc >> 3, c16 = cc & 7;
                    cp_async16(sB + (uint32_t)(n * 144 + c16 * 16),
                               B + (size_t)(col0 + n) * K + k0 + c16 * 8);
                }
            }
        };

        load_stage(0, 0);
        cp_commit();
        load_stage(1, 1);
        cp_commit();

        for (int kt = 0; kt < KT; kt++) {
            if (kt + 1 < KT) cp_wait<1>(); else cp_wait<0>();
            __syncthreads();
            if (kt + 2 < KT) { load_stage((kt + 2) % NSTAGE, kt + 2); cp_commit(); }

            uint32_t sA = smem_u32(smraw) + (kt % NSTAGE) * STAGE_BYTES;
            uint32_t sB = sA + A_BYTES;

#pragma unroll
            for (int kk = 0; kk < 4; kk++) {
                uint32_t kb = (uint32_t)(kk * 32);
                uint32_t af[4][4], bf[8][2];
#pragma unroll
                for (int mt = 0; mt < 4; mt++)
                    ldsm_x4(af[mt][0], af[mt][1], af[mt][2], af[mt][3],
                            sA + aoff[mt] + kb);
#pragma unroll
                for (int p = 0; p < 4; p++)
                    ldsm_x4(bf[2 * p][0], bf[2 * p][1], bf[2 * p + 1][0], bf[2 * p + 1][1],
                            sB + boff[p] + kb);
#pragma unroll
                for (int mt = 0; mt < 4; mt++)
#pragma unroll
                    for (int nt = 0; nt < 8; nt++)
                        mma16816(acc[mt][nt][0], acc[mt][nt][1], acc[mt][nt][2], acc[mt][nt][3],
                                 af[mt][0], af[mt][1], af[mt][2], af[mt][3],
                                 bf[nt][0], bf[nt][1]);
            }
        }

#pragma unroll
        for (int mt = 0; mt < 4; mt++) {
            int row = row0 + wm * 64 + mt * 16 + g;
#pragma unroll
            for (int nt = 0; nt < 8; nt++) {
                int col = col0 + wn * 64 + nt * 8 + tg * 2;
                float v0 = acc[mt][nt][0], v1 = acc[mt][nt][1];
                float v2 = acc[mt][nt][2], v3 = acc[mt][nt][3];
                if (RELU) {
                    v0 = fmaxf(v0, 0.0f); v1 = fmaxf(v1, 0.0f);
                    v2 = fmaxf(v2, 0.0f); v3 = fmaxf(v3, 0.0f);
                }
                if (HOUT) {
                    __half* Ch = (__half*)Cv;
                    *(__half2*)(Ch + (size_t)row * Nd + col) = __floats2half2_rn(v0, v1);
                    *(__half2*)(Ch + (size_t)(row + 8) * Nd + col) = __floats2half2_rn(v2, v3);
                } else {
                    float* Cf = (float*)Cv;
                    *(float2*)(Cf + (size_t)row * Nd + col) = make_float2(v0, v1);
                    *(float2*)(Cf + (size_t)(row + 8) * Nd + col) = make_float2(v2, v3);
                }
            }
        }
        __syncthreads();
    }
}

// ---------------- weight transpose+convert ----------------
__global__ void tpose_qkv_kernel(const float* __restrict__ Wq, const float* __restrict__ Wk,
                                 const float* __restrict__ Wv) {
    __shared__ float t[32][33];
    int l = blockIdx.z / 3, blk = blockIdx.z % 3;
    const float* in = (blk == 0 ? Wq : (blk == 1 ? Wk : Wv)) + (size_t)l * HIDDEN * HIDDEN;
    __half* out = g_wrh + (size_t)l * WT_LAYER + L_QKV + (size_t)blk * HIDDEN * HIDDEN;
    int c0 = blockIdx.x * 32, r0 = blockIdx.y * 32;
    int tx = threadIdx.x, ty = threadIdx.y;
#pragma unroll
    for (int i = 0; i < 4; i++)
        t[ty + 8 * i][tx] = in[(size_t)(r0 + ty + 8 * i) * HIDDEN + c0 + tx];
    __syncthreads();
#pragma unroll
    for (int i = 0; i < 4; i++)
        out[(size_t)(c0 + ty + 8 * i) * HIDDEN + r0 + tx] = __float2half(t[tx][ty + 8 * i]);
}

__global__ void tpose_kernel(const float* __restrict__ in, __half* __restrict__ out,
                             int rows, int cols, size_t in_ls, size_t out_ls) {
    __shared__ float t[32][33];
    in  += (size_t)blockIdx.z * in_ls;
    out += (size_t)blockIdx.z * out_ls;
    int c0 = blockIdx.x * 32, r0 = blockIdx.y * 32;
    int tx = threadIdx.x, ty = threadIdx.y;
#pragma unroll
    for (int i = 0; i < 4; i++)
        t[ty + 8 * i][tx] = in[(size_t)(r0 + ty + 8 * i) * cols + c0 + tx];
    __syncthreads();
#pragma unroll
    for (int i = 0; i < 4; i++)
        out[(size_t)(c0 + ty + 8 * i) * rows + r0 + tx] = __float2half(t[tx][ty + 8 * i]);
}

// ---------------- CSR build ----------------
__global__ void csr_count_kernel(const int* __restrict__ dst) {
    int e = blockIdx.x * blockDim.x + threadIdx.x;
    if (e < NE) atomicAdd(&g_deg[dst[e]], 1);
}
__global__ void csr_scan_kernel() {
    __shared__ int part[1024];
    int t = threadIdx.x;
    const int CH = (N_NODES + 1023) / 1024;
    int s = 0;
#pragma unroll
    for (int i = 0; i < CH; i++) {
        int idx = t * CH + i;
        if (idx < N_NODES) s += g_deg[idx];
    }
    part[t] = s;
    __syncthreads();
    if (t == 0) {
        int acc = 0;
        for (int i = 0; i < 1024; i++) { int v = part[i]; part[i] = acc; acc += v; }
        g_off[N_NODES] = acc;
    }
    __syncthreads();
    int acc = part[t];
#pragma unroll
    for (int i = 0; i < CH; i++) {
        int idx = t * CH + i;
        if (idx < N_NODES) { g_off[idx] = acc; acc += g_deg[idx]; }
    }
}
__global__ void csr_scatter_kernel(const int* __restrict__ dst) {
    int e = blockIdx.x * blockDim.x + threadIdx.x;
    if (e < NE) {
        int d = dst[e];
        int pos = g_off[d] + atomicAdd(&g_cur[d], 1);
        g_eid[pos] = e;
    }
}

// ---------------- edge attention: warp/node, online softmax, prefetched gathers -------
__global__ __launch_bounds__(256)
void edge_attn_kernel(const int* __restrict__ src, const int* __restrict__ rel) {
    int node = (blockIdx.x * blockDim.x + threadIdx.x) >> 5;
    if (node >= N_NODES) return;
    int lane = threadIdx.x & 31;
    int h = lane >> 2;
    int off = h * DKEY + (lane & 3) * 16;

    int beg = g_off[node], end = g_off[node + 1];
    __half2* wvp = (__half2*)(g_wvh + (size_t)node * HIDDEN + off);

    if (beg == end) {
        __half2 z2 = __floats2half2_rn(0.f, 0.f);
#pragma unroll
        for (int j = 0; j < 8; j++) wvp[j] = z2;
        return;
    }

    float qf[16];
    {
        const uint4* qp = (const uint4*)(g_qkvh + (size_t)node * QKVDIM + off);
#pragma unroll
        for (int j = 0; j < 2; j++) {
            uint4 raw = qp[j];
            const __half2* hv = (const __half2*)&raw;
#pragma unroll
            for (int jj = 0; jj < 4; jj++) {
                float2 f = __half22float2(hv[jj]);
                qf[j * 8 + jj * 2 + 0] = f.x;
                qf[j * 8 + jj * 2 + 1] = f.y;
            }
        }
    }

    float mx = -3.402823466e+38f;
    float z = 0.0f;
    float wa[16];
#pragma unroll
    for (int j = 0; j < 16; j++) wa[j] = 0.0f;

    // software-pipelined gather: load edge i+1 while computing edge i
    uint4 kr[2], vr[2], rr[2];
    {
        int e = g_eid[beg];
        int s = src[e], r = rel[e];
        const uint4* kp = (const uint4*)(g_qkvh + (size_t)s * QKVDIM + HIDDEN + off);
        const uint4* vp = (const uint4*)(g_qkvh + (size_t)s * QKVDIM + 2 * HIDDEN + off);
        const uint4* rp = (const uint4*)(g_relh + (size_t)r * HIDDEN + off);
        kr[0] = kp[0]; kr[1] = kp[1];
        vr[0] = vp[0]; vr[1] = vp[1];
        rr[0] = rp[0]; rr[1] = rp[1];
    }

    for (int i = beg; i < end; i++) {
        uint4 kn[2], vn[2], rn[2];
        if (i + 1 < end) {
            int e = g_eid[i + 1];
            int s = src[e], r = rel[e];
            const uint4* kp = (const uint4*)(g_qkvh + (size_t)s * QKVDIM + HIDDEN + off);
            const uint4* vp = (const uint4*)(g_qkvh + (size_t)s * QKVDIM + 2 * HIDDEN + off);
            const uint4* rp = (const uint4*)(g_relh + (size_t)r * HIDDEN + off);
            kn[0] = kp[0]; kn[1] = kp[1];
            vn[0] = vp[0]; vn[1] = vp[1];
            rn[0] = rp[0]; rn[1] = rp[1];
        }

        float tmp[16];
        float acc = 0.0f;
#pragma unroll
        for (int j = 0; j < 2; j++) {
            const __half2* kh = (const __half2*)&kr[j];
            const __half2* vh = (const __half2*)&vr[j];
            const __half2* rh = (const __half2*)&rr[j];
#pragma unroll
            for (int jj = 0; jj < 4; jj++) {
                float2 kf = __half22float2(kh[jj]);
                float2 vf = __half22float2(vh[jj]);
                float2 rf = __half22float2(rh[jj]);
                int o = j * 8 + jj * 2;
                acc += (kf.x + rf.x) * qf[o] + (kf.y + rf.y) * qf[o + 1];
                tmp[o]     = vf.x + rf.x;
                tmp[o + 1] = vf.y + rf.y;
            }
        }
        acc += __shfl_xor_sync(0xffffffffu, acc, 1);
        acc += __shfl_xor_sync(0xffffffffu, acc, 2);
        float sc = acc * SCALE;

        float m2 = fmaxf(mx, sc);
        float corr = expf(mx - m2);
        float ex = expf(sc - m2);
        z = z * corr + ex;
#pragma unroll
        for (int j = 0; j < 16; j++) wa[j] = wa[j] * corr + ex * tmp[j];
        mx = m2;

        if (i + 1 < end) {
            kr[0] = kn[0]; kr[1] = kn[1];
            vr[0] = vn[0]; vr[1] = vn[1];
            rr[0] = rn[0]; rr[1] = rn[1];
        }
    }

    float inv = 1.0f / (z + 1e-9f);
#pragma unroll
    for (int j = 0; j < 8; j++)
        wvp[j] = __floats2half2_rn(wa[2 * j] * inv, wa[2 * j + 1] * inv);
}

// ---------------- misc ----------------
__global__ void copy_x_zero_kernel(const float* __restrict__ x,
                                   const float* __restrict__ rel_embed,
                                   const float* __restrict__ bq,
                                   const float* __restrict__ bk,
                                   const float* __restrict__ bv) {
    int i = blockIdx.x * blockDim.x + threadIdx.x;
    if (i < N_NODES * HIDDEN) {
        float v = x[i];
        g_x[i] = v;
        g_xh[i] = __float2half(v);
    }
    if (i < NREL * HIDDEN) g_relh[i] = __float2half(rel_embed[i]);
    if (i < N_NODES) { g_deg[i] = 0; g_cur[i] = 0; }
    if (i < NLAYER * QKVDIM) {
        int l = i / QKVDIM, n = i % QKVDIM;
        int blk = n / HIDDEN, col = n % HIDDEN;
        const float* b = blk == 0 ? bq : (blk == 1 ? bk : bv);
        g_bqkv[i] = b[l * HIDDEN + col];
    }
}

// LN(residual a_f32 + b_f16) -> fp32 out + fp16 shadow
__global__ void ln_kernel(const float* __restrict__ A, const __half* __restrict__ B,
                          const float* __restrict__ gam, const float* __restrict__ bet,
                          float* __restrict__ out, __half* __restrict__ out16) {
    int n = blockIdx.x;
    int t = threadIdx.x;
    const float4 a = *(const float4*)(A + (size_t)n * HIDDEN + t * 4);
    const __half2* bh = (const __half2*)(B + (size_t)n * HIDDEN + t * 4);
    float2 b01 = __half22float2(bh[0]);
    float2 b23 = __half22float2(bh[1]);
    float v0 = a.x + b01.x, v1 = a.y + b01.y, v2 = a.z + b23.x, v3 = a.w + b23.y;
    float s  = v0 + v1 + v2 + v3;
    float sq = v0 * v0 + v1 * v1 + v2 * v2 + v3 * v3;
#pragma unroll
    for (int o = 16; o > 0; o >>= 1) {
        s  += __shfl_xor_sync(0xffffffffu, s, o);
        sq += __shfl_xor_sync(0xffffffffu, sq, o);
    }
    __shared__ float ss[4], ssq[4];
    int w = t >> 5, l = t & 31;
    if (l == 0) { ss[w] = s; ssq[w] = sq; }
    __syncthreads();
    s  = ss[0] + ss[1] + ss[2] + ss[3];
    sq = ssq[0] + ssq[1] + ssq[2] + ssq[3];
    float mean = s * (1.0f / HIDDEN);
    float var  = sq * (1.0f / HIDDEN) - mean * mean;
    if (var < 0.0f) var = 0.0f;
    float inv = rsqrtf(var + 1e-5f);
    const float4 g4 = *(const float4*)(gam + t * 4);
    const float4 b4 = *(const float4*)(bet + t * 4);
    float4 o4;
    o4.x = (v0 - mean) * inv * g4.x + b4.x;
    o4.y = (v1 - mean) * inv * g4.y + b4.y;
    o4.z = (v2 - mean) * inv * g4.z + b4.z;
    o4.w = (v3 - mean) * inv * g4.w + b4.w;
    *(float4*)(out + (size_t)n * HIDDEN + t * 4) = o4;
    __half2* p16 = (__half2*)(out16 + (size_t)n * HIDDEN + t * 4);
    p16[0] = __floats2half2_rn(o4.x, o4.y);
    p16[1] = __floats2half2_rn(o4.z, o4.w);
}

// ---------------- host driver ----------------
static inline void* sym_addr(const void* s) {
    void* p = nullptr;
    cudaGetSymbolAddress(&p, s);
    return p;
}

extern "C" void kernel_launch(void* const* d_in, const int* in_sizes, int n_in,
                              void* d_out, int out_size) {
    const float* x         = (const float*)d_in[0];
    const int*   relations = (const int*)d_in[1];
    const int*   src       = (const int*)d_in[2];
    const int*   dst       = (const int*)d_in[3];
    const float* rel_embed = (const float*)d_in[4];
    const float* Wq = (const float*)d_in[5];  const float* bq = (const float*)d_in[6];
    const float* Wk = (const float*)d_in[7];  const float* bk = (const float*)d_in[8];
    const float* Wv = (const float*)d_in[9];  const float* bv = (const float*)d_in[10];
    const float* Wo = (const float*)d_in[11]; const float* bo = (const float*)d_in[12];
    const float* W1 = (const float*)d_in[13]; const float* b1 = (const float*)d_in[14];
    const float* W2 = (const float*)d_in[15]; const float* b2 = (const float*)d_in[16];
    const float* g1 = (const float*)d_in[17]; const float* be1 = (const float*)d_in[18];
    const float* g2 = (const float*)d_in[19]; const float* be2 = (const float*)d_in[20];
    float* out = (float*)d_out;

    float*  xb    = (float*)sym_addr(g_x);
    __half* xhb   = (__half*)sym_addr(g_xh);
    __half* qkvhb = (__half*)sym_addr(g_qkvh);
    __half* wvhb  = (__half*)sym_addr(g_wvh);
    __half* ohb   = (__half*)sym_addr(g_oh);
    float*  hb    = (float*)sym_addr(g_h);
    __half* hhb   = (__half*)sym_addr(g_hh);
    __half* ffhb  = (__half*)sym_addr(g_ffh);
    __half* f2hb  = (__half*)sym_addr(g_f2h);
    __half* wrhb  = (__half*)sym_addr(g_wrh);
    float*  bqkvb = (float*)sym_addr(g_bqkv);

    cudaFuncSetAttribute(gemm_h<0,1>, cudaFuncAttributeMaxDynamicSharedMemorySize, GEMM_SMEM);
    cudaFuncSetAttribute(gemm_h<1,1>, cudaFuncAttributeMaxDynamicSharedMemorySize, GEMM_SMEM);

    int nsm = 148;
    cudaDeviceGetAttribute(&nsm, cudaDevAttrMultiProcessorCount, 0);
    const int pgrid = 2 * nsm;

    const int nh = N_NODES * HIDDEN;
    int attn_blocks = (N_NODES * 32 + 255) / 256;
    auto gsz = [&](int ntiles) { return ntiles < pgrid ? ntiles : pgrid; };
    const int t512 = (HIDDEN / 128) * (MPAD / 128);
    const int tQKV = (QKVDIM / 128) * (MPAD / 128);
    const int tFF  = (FFDIM / 128) * (MPAD / 128);

    dim3 tb(32, 8);

    // launch order: idx 3 = layer-0 QKV GEMM (ncu skip captures it)
    copy_x_zero_kernel<<<(nh + 255) / 256, 256>>>(x, rel_embed, bq, bk, bv);      // 0
    tpose_qkv_kernel<<<dim3(16, 16, 3 * NLAYER), tb>>>(Wq, Wk, Wv);               // 1
    csr_count_kernel<<<(NE + 255) / 256, 256>>>(dst);                             // 2
    gemm_h<0,1><<<gsz(tQKV), 128, GEMM_SMEM>>>(xhb, wrhb + L_QKV, bqkvb, qkvhb,
                                               HIDDEN, QKVDIM);                  // 3
    tpose_kernel<<<dim3(16, 16, NLAYER), tb>>>(Wo, wrhb + L_O, HIDDEN, HIDDEN,
                                               (size_t)HIDDEN * HIDDEN, WT_LAYER);// 4
    tpose_kernel<<<dim3(64, 16, NLAYER), tb>>>(W1, wrhb + L_W1, HIDDEN, FFDIM,
                                               (size_t)HIDDEN * FFDIM, WT_LAYER); // 5
    tpose_kernel<<<dim3(16, 64, NLAYER), tb>>>(W2, wrhb + L_W2, FFDIM, HIDDEN,
                                               (size_t)FFDIM * HIDDEN, WT_LAYER); // 6
    csr_scan_kernel<<<1, 1024>>>();                                               // 7
    csr_scatter_kernel<<<(NE + 255) / 256, 256>>>(dst);                           // 8

    for (int i = 0; i < NLAYER; i++) {
        __half* wl = wrhb + (size_t)i * WT_LAYER;

        if (i > 0)
            gemm_h<0,1><<<gsz(tQKV), 128, GEMM_SMEM>>>(xhb, wl + L_QKV,
                                                       bqkvb + i * QKVDIM, qkvhb,
                                                       HIDDEN, QKVDIM);

        edge_attn_kernel<<<attn_blocks, 256>>>(src, relations);

        gemm_h<0,1><<<gsz(t512), 128, GEMM_SMEM>>>(wvhb, wl + L_O, bo + i * HIDDEN,
                                                   ohb, HIDDEN, HIDDEN);
        ln_kernel<<<N_NODES, 128>>>(xb, ohb, g1 + i * HIDDEN, be1 + i * HIDDEN, hb, hhb);

        gemm_h<1,1><<<gsz(tFF), 128, GEMM_SMEM>>>(hhb, wl + L_W1, b1 + i * FFDIM,
                                                  ffhb, HIDDEN, FFDIM);
        gemm_h<0,1><<<gsz(t512), 128, GEMM_SMEM>>>(ffhb, wl + L_W2, b2 + i * HIDDEN,
                                                   f2hb, FFDIM, HIDDEN);

        float* dest = (i == NLAYER - 1) ? out : xb;
        ln_kernel<<<N_NODES, 128>>>(hb, f2hb, g2 + i * HIDDEN, be2 + i * HIDDEN,
                                    dest, xhb);
    }
}

// round 17
// speedup vs baseline: 1.0232x; 1.0232x over previous
#include <cuda_runtime.h>
#include <cuda_fp16.h>
#include <math.h>
#include <stdint.h>

#define N_NODES 20000
#define NE      160000
#define HIDDEN  512
#define QKVDIM  1536
#define NREL    128
#define NHEAD   8
#define DKEY    64
#define NLAYER  4
#define FFDIM   2048
#define MPAD    20096   // 157 * 128
#define SCALE   0.125f

// ---------------- device scratch ----------------
__device__ float  g_x  [(size_t)MPAD * HIDDEN];
__device__ __half g_xh [(size_t)MPAD * HIDDEN];
__device__ __half g_qkvh[(size_t)MPAD * QKVDIM];
__device__ __half g_wvh[(size_t)MPAD * HIDDEN];
__device__ __half g_oh [(size_t)MPAD * HIDDEN];
__device__ float  g_h  [(size_t)MPAD * HIDDEN];
__device__ __half g_hh [(size_t)MPAD * HIDDEN];
__device__ __half g_ffh[(size_t)MPAD * FFDIM];
__device__ __half g_f2h[(size_t)MPAD * HIDDEN];
__device__ __half g_relh[NREL * HIDDEN];

// CSR
__device__ int g_deg[N_NODES];
__device__ int g_cur[N_NODES];
__device__ int g_off[N_NODES + 1];
__device__ int g_eid[NE];

// fp16 weights, transposed to [N][K] per GEMM. per layer: QKV, O, W1, W2
#define L_QKV 0
#define L_O   (HIDDEN * QKVDIM)
#define L_W1  (L_O + HIDDEN * HIDDEN)
#define L_W2  (L_W1 + HIDDEN * FFDIM)
#define WT_LAYER (L_W2 + FFDIM * HIDDEN)
__device__ __half g_wrh[(size_t)NLAYER * WT_LAYER];
__device__ float  g_bqkv[NLAYER * QKVDIM];

// ---------------- helpers ----------------
__device__ __forceinline__ uint32_t smem_u32(const void* p) {
    return (uint32_t)__cvta_generic_to_shared(p);
}
__device__ __forceinline__ void cp_async16(uint32_t smem_dst, const void* gmem_src) {
    asm volatile("cp.async.cg.shared.global [%0], [%1], 16;\n" :: "r"(smem_dst), "l"(gmem_src));
}
__device__ __forceinline__ void cp_commit() {
    asm volatile("cp.async.commit_group;\n");
}
template <int N>
__device__ __forceinline__ void cp_wait() {
    asm volatile("cp.async.wait_group %0;\n" :: "n"(N));
}
__device__ __forceinline__ void mma16816(float& d0, float& d1, float& d2, float& d3,
                                         uint32_t a0, uint32_t a1, uint32_t a2, uint32_t a3,
                                         uint32_t b0, uint32_t b1) {
    asm volatile(
        "mma.sync.aligned.m16n8k16.row.col.f32.f16.f16.f32 "
        "{%0,%1,%2,%3}, {%4,%5,%6,%7}, {%8,%9}, {%0,%1,%2,%3};\n"
        : "+f"(d0), "+f"(d1), "+f"(d2), "+f"(d3)
        : "r"(a0), "r"(a1), "r"(a2), "r"(a3), "r"(b0), "r"(b1));
}
__device__ __forceinline__ void ldsm_x4(uint32_t& r0, uint32_t& r1, uint32_t& r2, uint32_t& r3,
                                        uint32_t addr) {
    asm volatile("ldmatrix.sync.aligned.m8n8.x4.shared.b16 {%0,%1,%2,%3}, [%4];"
                 : "=r"(r0), "=r"(r1), "=r"(r2), "=r"(r3) : "r"(addr));
}

// ---------------- persistent fp16 GEMM (fp32 accum) ----------------
// CTA 128x128, 4 warps (2x2), warp 64x64, K-chunk 64, 3-stage cp.async, ldmatrix.x4.
#define ASH 72
#define A_BYTES (128 * ASH * 2)      // 18432
#define STAGE_BYTES (2 * A_BYTES)    // 36864
#define NSTAGE 3
#define GEMM_SMEM (NSTAGE * STAGE_BYTES)   // 110,592 B

template<int RELU, int HOUT>
__global__ __launch_bounds__(128, 2)
void gemm_h(const __half* __restrict__ A, const __half* __restrict__ B,
            const float* __restrict__ bias, void* __restrict__ Cv,
            int K, int Nd) {
    extern __shared__ char smraw[];

    int tid = threadIdx.x;
    int warp = tid >> 5, lane = tid & 31;
    int wm = warp >> 1, wn = warp & 1;
    int g = lane >> 2, tg = lane & 3;
    int mi = lane >> 3, lr = lane & 7;
    const int KT = K >> 6;
    const int ntx = Nd >> 7;
    const int num_tiles = ntx * (MPAD >> 7);

    uint32_t aoff[4];
#pragma unroll
    for (int mt = 0; mt < 4; mt++)
        aoff[mt] = (uint32_t)((wm * 64 + mt * 16 + (mi & 1) * 8 + lr) * 144 + (mi >> 1) * 16);
    uint32_t boff[4];
#pragma unroll
    for (int p = 0; p < 4; p++)
        boff[p] = (uint32_t)((wn * 64 + p * 16 + (mi >> 1) * 8 + lr) * 144 + (mi & 1) * 16);

    for (int tile = blockIdx.x; tile < num_tiles; tile += gridDim.x) {
        int row0 = (tile / ntx) * 128;
        int col0 = (tile % ntx) * 128;

        float acc[4][8][4];
#pragma unroll
        for (int nt = 0; nt < 8; nt++) {
            int col = col0 + wn * 64 + nt * 8 + tg * 2;
            float b0 = bias[col], b1 = bias[col + 1];
#pragma unroll
            for (int mt = 0; mt < 4; mt++) {
                acc[mt][nt][0] = b0; acc[mt][nt][1] = b1;
                acc[mt][nt][2] = b0; acc[mt][nt][3] = b1;
            }
        }

        auto load_stage = [&](int stage, int kt) {
            uint32_t sA = smem_u32(smraw) + stage * STAGE_BYTES;
            uint32_t sB = sA + A_BYTES;
            int k0 = kt << 6;
#pragma unroll
            for (int i = 0; i < 16; i++) {
                int c = tid + i * 128;
                if (c < 1024) {
                    int row = c >> 3, c16 = c & 7;
                    cp_async16(sA + (uint32_t)(row * 144 + c16 * 16),
                               A + (size_t)(row0 + row) * K + k0 + c16 * 8);
                } else {
                    int cc = c - 1024;
                    int n = cc >> 3, c16 = cc & 7;
                    cp_async16(sB + (uint32_t)(n * 144 + c16 * 16),
                               B + (size_t)(col0 + n) * K + k0 + c16 * 8);
                }
            }
        };

        load_stage(0, 0);
        cp_commit();
        load_stage(1, 1);
        cp_commit();

        for (int kt = 0; kt < KT; kt++) {
            if (kt + 1 < KT) cp_wait<1>(); else cp_wait<0>();
            __syncthreads();
            if (kt + 2 < KT) { load_stage((kt + 2) % NSTAGE, kt + 2); cp_commit(); }

            uint32_t sA = smem_u32(smraw) + (kt % NSTAGE) * STAGE_BYTES;
            uint32_t sB = sA + A_BYTES;

#pragma unroll
            for (int kk = 0; kk < 4; kk++) {
                uint32_t kb = (uint32_t)(kk * 32);
                uint32_t af[4][4], bf[8][2];
#pragma unroll
                for (int mt = 0; mt < 4; mt++)
                    ldsm_x4(af[mt][0], af[mt][1], af[mt][2], af[mt][3],
                            sA + aoff[mt] + kb);
#pragma unroll
                for (int p = 0; p < 4; p++)
                    ldsm_x4(bf[2 * p][0], bf[2 * p][1], bf[2 * p + 1][0], bf[2 * p + 1][1],
                            sB + boff[p] + kb);
#pragma unroll
                for (int mt = 0; mt < 4; mt++)
#pragma unroll
                    for (int nt = 0; nt < 8; nt++)
                        mma16816(acc[mt][nt][0], acc[mt][nt][1], acc[mt][nt][2], acc[mt][nt][3],
                                 af[mt][0], af[mt][1], af[mt][2], af[mt][3],
                                 bf[nt][0], bf[nt][1]);
            }
        }

#pragma unroll
        for (int mt = 0; mt < 4; mt++) {
            int row = row0 + wm * 64 + mt * 16 + g;
#pragma unroll
            for (int nt = 0; nt < 8; nt++) {
                int col = col0 + wn * 64 + nt * 8 + tg * 2;
                float v0 = acc[mt][nt][0], v1 = acc[mt][nt][1];
                float v2 = acc[mt][nt][2], v3 = acc[mt][nt][3];
                if (RELU) {
                    v0 = fmaxf(v0, 0.0f); v1 = fmaxf(v1, 0.0f);
                    v2 = fmaxf(v2, 0.0f); v3 = fmaxf(v3, 0.0f);
                }
                if (HOUT) {
                    __half* Ch = (__half*)Cv;
                    *(__half2*)(Ch + (size_t)row * Nd + col) = __floats2half2_rn(v0, v1);
                    *(__half2*)(Ch + (size_t)(row + 8) * Nd + col) = __floats2half2_rn(v2, v3);
                } else {
                    float* Cf = (float*)Cv;
                    *(float2*)(Cf + (size_t)row * Nd + col) = make_float2(v0, v1);
                    *(float2*)(Cf + (size_t)(row + 8) * Nd + col) = make_float2(v2, v3);
                }
            }
        }
        __syncthreads();
    }
}

// ---------------- weight transpose+convert ----------------
__global__ void tpose_qkv_kernel(const float* __restrict__ Wq, const float* __restrict__ Wk,
                                 const float* __restrict__ Wv) {
    __shared__ float t[32][33];
    int l = blockIdx.z / 3, blk = blockIdx.z % 3;
    const float* in = (blk == 0 ? Wq : (blk == 1 ? Wk : Wv)) + (size_t)l * HIDDEN * HIDDEN;
    __half* out = g_wrh + (size_t)l * WT_LAYER + L_QKV + (size_t)blk * HIDDEN * HIDDEN;
    int c0 = blockIdx.x * 32, r0 = blockIdx.y * 32;
    int tx = threadIdx.x, ty = threadIdx.y;
#pragma unroll
    for (int i = 0; i < 4; i++)
        t[ty + 8 * i][tx] = in[(size_t)(r0 + ty + 8 * i) * HIDDEN + c0 + tx];
    __syncthreads();
#pragma unroll
    for (int i = 0; i < 4; i++)
        out[(size_t)(c0 + ty + 8 * i) * HIDDEN + r0 + tx] = __float2half(t[tx][ty + 8 * i]);
}

__global__ void tpose_kernel(const float* __restrict__ in, __half* __restrict__ out,
                             int rows, int cols, size_t in_ls, size_t out_ls) {
    __shared__ float t[32][33];
    in  += (size_t)blockIdx.z * in_ls;
    out += (size_t)blockIdx.z * out_ls;
    int c0 = blockIdx.x * 32, r0 = blockIdx.y * 32;
    int tx = threadIdx.x, ty = threadIdx.y;
#pragma unroll
    for (int i = 0; i < 4; i++)
        t[ty + 8 * i][tx] = in[(size_t)(r0 + ty + 8 * i) * cols + c0 + tx];
    __syncthreads();
#pragma unroll
    for (int i = 0; i < 4; i++)
        out[(size_t)(c0 + ty + 8 * i) * rows + r0 + tx] = __float2half(t[tx][ty + 8 * i]);
}

// ---------------- CSR build ----------------
__global__ void csr_count_kernel(const int* __restrict__ dst) {
    int e = blockIdx.x * blockDim.x + threadIdx.x;
    if (e < NE) atomicAdd(&g_deg[dst[e]], 1);
}
__global__ void csr_scan_kernel() {
    __shared__ int part[1024];
    int t = threadIdx.x;
    const int CH = (N_NODES + 1023) / 1024;
    int s = 0;
#pragma unroll
    for (int i = 0; i < CH; i++) {
        int idx = t * CH + i;
        if (idx < N_NODES) s += g_deg[idx];
    }
    part[t] = s;
    __syncthreads();
    if (t == 0) {
        int acc = 0;
        for (int i = 0; i < 1024; i++) { int v = part[i]; part[i] = acc; acc += v; }
        g_off[N_NODES] = acc;
    }
    __syncthreads();
    int acc = part[t];
#pragma unroll
    for (int i = 0; i < CH; i++) {
        int idx = t * CH + i;
        if (idx < N_NODES) { g_off[idx] = acc; acc += g_deg[idx]; }
    }
}
__global__ void csr_scatter_kernel(const int* __restrict__ dst) {
    int e = blockIdx.x * blockDim.x + threadIdx.x;
    if (e < NE) {
        int d = dst[e];
        int pos = g_off[d] + atomicAdd(&g_cur[d], 1);
        g_eid[pos] = e;
    }
}

// ---------------- edge attention: warp/node, dual online-softmax chains ---------------
__global__ __launch_bounds__(256)
void edge_attn_kernel(const int* __restrict__ src, const int* __restrict__ rel) {
    int node = (blockIdx.x * blockDim.x + threadIdx.x) >> 5;
    if (node >= N_NODES) return;
    int lane = threadIdx.x & 31;
    int h = lane >> 2;
    int off = h * DKEY + (lane & 3) * 16;

    int beg = g_off[node], end = g_off[node + 1];
    __half2* wvp = (__half2*)(g_wvh + (size_t)node * HIDDEN + off);

    if (beg == end) {
        __half2 z2h = __floats2half2_rn(0.f, 0.f);
#pragma unroll
        for (int j = 0; j < 8; j++) wvp[j] = z2h;
        return;
    }

    float qf[16];
    {
        const uint4* qp = (const uint4*)(g_qkvh + (size_t)node * QKVDIM + off);
#pragma unroll
        for (int j = 0; j < 2; j++) {
            uint4 raw = qp[j];
            const __half2* hv = (const __half2*)&raw;
#pragma unroll
            for (int jj = 0; jj < 4; jj++) {
                float2 f = __half22float2(hv[jj]);
                qf[j * 8 + jj * 2 + 0] = f.x;
                qf[j * 8 + jj * 2 + 1] = f.y;
            }
        }
    }

    const float NEG = -3.402823466e+38f;
    int len = end - beg;
    int half1 = (len + 1) >> 1;           // chain A: [beg, beg+half1)
    int mid = beg + half1;                // chain B: [mid, end)

    float mA = NEG, zA = 0.0f, mB = NEG, zB = 0.0f;
    float waA[16], waB[16];
#pragma unroll
    for (int j = 0; j < 16; j++) { waA[j] = 0.0f; waB[j] = 0.0f; }

    for (int t = 0; t < half1; t++) {
        int iA = beg + t;
        int iB = mid + t;
        bool hasB = iB < end;

        // issue both edges' gathers up front (MLP 2)
        int eA = g_eid[iA];
        int sA = src[eA], rA = rel[eA];
        const uint4* kpA = (const uint4*)(g_qkvh + (size_t)sA * QKVDIM + HIDDEN + off);
        const uint4* vpA = (const uint4*)(g_qkvh + (size_t)sA * QKVDIM + 2 * HIDDEN + off);
        const uint4* rpA = (const uint4*)(g_relh + (size_t)rA * HIDDEN + off);
        uint4 kA0 = kpA[0], kA1 = kpA[1], vA0 = vpA[0], vA1 = vpA[1], rA0 = rpA[0], rA1 = rpA[1];

        uint4 kB0, kB1, vB0, vB1, rB0, rB1;
        if (hasB) {
            int eB = g_eid[iB];
            int sB = src[eB], rB = rel[eB];
            const uint4* kpB = (const uint4*)(g_qkvh + (size_t)sB * QKVDIM + HIDDEN + off);
            const uint4* vpB = (const uint4*)(g_qkvh + (size_t)sB * QKVDIM + 2 * HIDDEN + off);
            const uint4* rpB = (const uint4*)(g_relh + (size_t)rB * HIDDEN + off);
            kB0 = kpB[0]; kB1 = kpB[1]; vB0 = vpB[0]; vB1 = vpB[1]; rB0 = rpB[0]; rB1 = rpB[1];
        }

        // ---- chain A ----
        {
            uint4 kr[2] = {kA0, kA1}, vr[2] = {vA0, vA1}, rr[2] = {rA0, rA1};
            float tmp[16], acc = 0.0f;
#pragma unroll
            for (int j = 0; j < 2; j++) {
                const __half2* kh = (const __half2*)&kr[j];
                const __half2* vh = (const __half2*)&vr[j];
                const __half2* rh = (const __half2*)&rr[j];
#pragma unroll
                for (int jj = 0; jj < 4; jj++) {
                    float2 kf = __half22float2(kh[jj]);
                    float2 vf = __half22float2(vh[jj]);
                    float2 rf = __half22float2(rh[jj]);
                    int o = j * 8 + jj * 2;
                    acc += (kf.x + rf.x) * qf[o] + (kf.y + rf.y) * qf[o + 1];
                    tmp[o]     = vf.x + rf.x;
                    tmp[o + 1] = vf.y + rf.y;
                }
            }
            acc += __shfl_xor_sync(0xffffffffu, acc, 1);
            acc += __shfl_xor_sync(0xffffffffu, acc, 2);
            float sc = acc * SCALE;
            float m2 = fmaxf(mA, sc);
            float corr = expf(mA - m2);
            float ex = expf(sc - m2);
            zA = zA * corr + ex;
#pragma unroll
            for (int j = 0; j < 16; j++) waA[j] = waA[j] * corr + ex * tmp[j];
            mA = m2;
        }

        // ---- chain B ----
        if (hasB) {
            uint4 kr[2] = {kB0, kB1}, vr[2] = {vB0, vB1}, rr[2] = {rB0, rB1};
            float tmp[16], acc = 0.0f;
#pragma unroll
            for (int j = 0; j < 2; j++) {
                const __half2* kh = (const __half2*)&kr[j];
                const __half2* vh = (const __half2*)&vr[j];
                const __half2* rh = (const __half2*)&rr[j];
#pragma unroll
                for (int jj = 0; jj < 4; jj++) {
                    float2 kf = __half22float2(kh[jj]);
                    float2 vf = __half22float2(vh[jj]);
                    float2 rf = __half22float2(rh[jj]);
                    int o = j * 8 + jj * 2;
                    acc += (kf.x + rf.x) * qf[o] + (kf.y + rf.y) * qf[o + 1];
                    tmp[o]     = vf.x + rf.x;
                    tmp[o + 1] = vf.y + rf.y;
                }
            }
            acc += __shfl_xor_sync(0xffffffffu, acc, 1);
            acc += __shfl_xor_sync(0xffffffffu, acc, 2);
            float sc = acc * SCALE;
            float m2 = fmaxf(mB, sc);
            float corr = expf(mB - m2);
            float ex = expf(sc - m2);
            zB = zB * corr + ex;
#pragma unroll
            for (int j = 0; j < 16; j++) waB[j] = waB[j] * corr + ex * tmp[j];
            mB = m2;
        }
    }

    // merge chains: e^(-inf) = 0 handles an empty chain B exactly
    float m = fmaxf(mA, mB);
    float cA = expf(mA - m);
    float cB = expf(mB - m);
    float z = zA * cA + zB * cB;
    float inv = 1.0f / (z + 1e-9f);
#pragma unroll
    for (int j = 0; j < 8; j++) {
        float w0 = (waA[2 * j]     * cA + waB[2 * j]     * cB) * inv;
        float w1 = (waA[2 * j + 1] * cA + waB[2 * j + 1] * cB) * inv;
        wvp[j] = __floats2half2_rn(w0, w1);
    }
}

// ---------------- misc ----------------
__global__ void copy_x_zero_kernel(const float* __restrict__ x,
                                   const float* __restrict__ rel_embed,
                                   const float* __restrict__ bq,
                                   const float* __restrict__ bk,
                                   const float* __restrict__ bv) {
    int i = blockIdx.x * blockDim.x + threadIdx.x;
    if (i < N_NODES * HIDDEN) {
        float v = x[i];
        g_x[i] = v;
        g_xh[i] = __float2half(v);
    }
    if (i < NREL * HIDDEN) g_relh[i] = __float2half(rel_embed[i]);
    if (i < N_NODES) { g_deg[i] = 0; g_cur[i] = 0; }
    if (i < NLAYER * QKVDIM) {
        int l = i / QKVDIM, n = i % QKVDIM;
        int blk = n / HIDDEN, col = n % HIDDEN;
        const float* b = blk == 0 ? bq : (blk == 1 ? bk : bv);
        g_bqkv[i] = b[l * HIDDEN + col];
    }
}

// LN(residual a_f32 + b_f16) -> fp32 out + fp16 shadow
__global__ void ln_kernel(const float* __restrict__ A, const __half* __restrict__ B,
                          const float* __restrict__ gam, const float* __restrict__ bet,
                          float* __restrict__ out, __half* __restrict__ out16) {
    int n = blockIdx.x;
    int t = threadIdx.x;
    const float4 a = *(const float4*)(A + (size_t)n * HIDDEN + t * 4);
    const __half2* bh = (const __half2*)(B + (size_t)n * HIDDEN + t * 4);
    float2 b01 = __half22float2(bh[0]);
    float2 b23 = __half22float2(bh[1]);
    float v0 = a.x + b01.x, v1 = a.y + b01.y, v2 = a.z + b23.x, v3 = a.w + b23.y;
    float s  = v0 + v1 + v2 + v3;
    float sq = v0 * v0 + v1 * v1 + v2 * v2 + v3 * v3;
#pragma unroll
    for (int o = 16; o > 0; o >>= 1) {
        s  += __shfl_xor_sync(0xffffffffu, s, o);
        sq += __shfl_xor_sync(0xffffffffu, sq, o);
    }
    __shared__ float ss[4], ssq[4];
    int w = t >> 5, l = t & 31;
    if (l == 0) { ss[w] = s; ssq[w] = sq; }
    __syncthreads();
    s  = ss[0] + ss[1] + ss[2] + ss[3];
    sq = ssq[0] + ssq[1] + ssq[2] + ssq[3];
    float mean = s * (1.0f / HIDDEN);
    float var  = sq * (1.0f / HIDDEN) - mean * mean;
    if (var < 0.0f) var = 0.0f;
    float inv = rsqrtf(var + 1e-5f);
    const float4 g4 = *(const float4*)(gam + t * 4);
    const float4 b4 = *(const float4*)(bet + t * 4);
    float4 o4;
    o4.x = (v0 - mean) * inv * g4.x + b4.x;
    o4.y = (v1 - mean) * inv * g4.y + b4.y;
    o4.z = (v2 - mean) * inv * g4.z + b4.z;
    o4.w = (v3 - mean) * inv * g4.w + b4.w;
    *(float4*)(out + (size_t)n * HIDDEN + t * 4) = o4;
    __half2* p16 = (__half2*)(out16 + (size_t)n * HIDDEN + t * 4);
    p16[0] = __floats2half2_rn(o4.x, o4.y);
    p16[1] = __floats2half2_rn(o4.z, o4.w);
}

// ---------------- host driver ----------------
static inline void* sym_addr(const void* s) {
    void* p = nullptr;
    cudaGetSymbolAddress(&p, s);
    return p;
}

extern "C" void kernel_launch(void* const* d_in, const int* in_sizes, int n_in,
                              void* d_out, int out_size) {
    const float* x         = (const float*)d_in[0];
    const int*   relations = (const int*)d_in[1];
    const int*   src       = (const int*)d_in[2];
    const int*   dst       = (const int*)d_in[3];
    const float* rel_embed = (const float*)d_in[4];
    const float* Wq = (const float*)d_in[5];  const float* bq = (const float*)d_in[6];
    const float* Wk = (const float*)d_in[7];  const float* bk = (const float*)d_in[8];
    const float* Wv = (const float*)d_in[9];  const float* bv = (const float*)d_in[10];
    const float* Wo = (const float*)d_in[11]; const float* bo = (const float*)d_in[12];
    const float* W1 = (const float*)d_in[13]; const float* b1 = (const float*)d_in[14];
    const float* W2 = (const float*)d_in[15]; const float* b2 = (const float*)d_in[16];
    const float* g1 = (const float*)d_in[17]; const float* be1 = (const float*)d_in[18];
    const float* g2 = (const float*)d_in[19]; const float* be2 = (const float*)d_in[20];
    float* out = (float*)d_out;

    float*  xb    = (float*)sym_addr(g_x);
    __half* xhb   = (__half*)sym_addr(g_xh);
    __half* qkvhb = (__half*)sym_addr(g_qkvh);
    __half* wvhb  = (__half*)sym_addr(g_wvh);
    __half* ohb   = (__half*)sym_addr(g_oh);
    float*  hb    = (float*)sym_addr(g_h);
    __half* hhb   = (__half*)sym_addr(g_hh);
    __half* ffhb  = (__half*)sym_addr(g_ffh);
    __half* f2hb  = (__half*)sym_addr(g_f2h);
    __half* wrhb  = (__half*)sym_addr(g_wrh);
    float*  bqkvb = (float*)sym_addr(g_bqkv);

    cudaFuncSetAttribute(gemm_h<0,1>, cudaFuncAttributeMaxDynamicSharedMemorySize, GEMM_SMEM);
    cudaFuncSetAttribute(gemm_h<1,1>, cudaFuncAttributeMaxDynamicSharedMemorySize, GEMM_SMEM);

    int nsm = 148;
    cudaDeviceGetAttribute(&nsm, cudaDevAttrMultiProcessorCount, 0);
    const int pgrid = 2 * nsm;

    const int nh = N_NODES * HIDDEN;
    int attn_blocks = (N_NODES * 32 + 255) / 256;
    auto gsz = [&](int ntiles) { return ntiles < pgrid ? ntiles : pgrid; };
    const int t512 = (HIDDEN / 128) * (MPAD / 128);
    const int tQKV = (QKVDIM / 128) * (MPAD / 128);
    const int tFF  = (FFDIM / 128) * (MPAD / 128);

    dim3 tb(32, 8);

    // launch order: idx 3 = layer-0 QKV GEMM (ncu skip captures it)
    copy_x_zero_kernel<<<(nh + 255) / 256, 256>>>(x, rel_embed, bq, bk, bv);      // 0
    tpose_qkv_kernel<<<dim3(16, 16, 3 * NLAYER), tb>>>(Wq, Wk, Wv);               // 1
    csr_count_kernel<<<(NE + 255) / 256, 256>>>(dst);                             // 2
    gemm_h<0,1><<<gsz(tQKV), 128, GEMM_SMEM>>>(xhb, wrhb + L_QKV, bqkvb, qkvhb,
                                               HIDDEN, QKVDIM);                  // 3
    tpose_kernel<<<dim3(16, 16, NLAYER), tb>>>(Wo, wrhb + L_O, HIDDEN, HIDDEN,
                                               (size_t)HIDDEN * HIDDEN, WT_LAYER);// 4
    tpose_kernel<<<dim3(64, 16, NLAYER), tb>>>(W1, wrhb + L_W1, HIDDEN, FFDIM,
                                               (size_t)HIDDEN * FFDIM, WT_LAYER); // 5
    tpose_kernel<<<dim3(16, 64, NLAYER), tb>>>(W2, wrhb + L_W2, FFDIM, HIDDEN,
                                               (size_t)FFDIM * HIDDEN, WT_LAYER); // 6
    csr_scan_kernel<<<1, 1024>>>();                                               // 7
    csr_scatter_kernel<<<(NE + 255) / 256, 256>>>(dst);                           // 8

    for (int i = 0; i < NLAYER; i++) {
        __half* wl = wrhb + (size_t)i * WT_LAYER;

        if (i > 0)
            gemm_h<0,1><<<gsz(tQKV), 128, GEMM_SMEM>>>(xhb, wl + L_QKV,
                                                       bqkvb + i * QKVDIM, qkvhb,
                                                       HIDDEN, QKVDIM);

        edge_attn_kernel<<<attn_blocks, 256>>>(src, relations);

        gemm_h<0,1><<<gsz(t512), 128, GEMM_SMEM>>>(wvhb, wl + L_O, bo + i * HIDDEN,
                                                   ohb, HIDDEN, HIDDEN);
        ln_kernel<<<N_NODES, 128>>>(xb, ohb, g1 + i * HIDDEN, be1 + i * HIDDEN, hb, hhb);

        gemm_h<1,1><<<gsz(tFF), 128, GEMM_SMEM>>>(hhb, wl + L_W1, b1 + i * FFDIM,
                                                  ffhb, HIDDEN, FFDIM);
        gemm_h<0,1><<<gsz(t512), 128, GEMM_SMEM>>>(ffhb, wl + L_W2, b2 + i * HIDDEN,
                                                   f2hb, FFDIM, HIDDEN);

        float* dest = (i == NLAYER - 1) ? out : xb;
        ln_kernel<<<N_NODES, 128>>>(hb, f2hb, g2 + i * HIDDEN, be2 + i * HIDDEN,
                                    dest, xhb);
    }
}